// round 3
// baseline (speedup 1.0000x reference)
#include <cuda_runtime.h>

#define NN 50000
#define NE 640000
#define NR 8
#define D1 128   // IN_DIM == HID_DIM
#define D2 64    // OUT_DIM

// Scratch (allocation-free rule: __device__ globals)
__device__ float g_rel1[(size_t)NR * NN * D1]; // 204.8 MB
__device__ float g_rel2[(size_t)NR * NN * D2]; // 102.4 MB
__device__ float g_h1[(size_t)NN * D1];        // 25.6 MB

// C[z] = (relu?)(A) @ W[z] (+ bias), A:[NN,128], W:[Z,128,DOUT], C:[Z,NN,DOUT]
template<int DOUT, bool RELU_IN, bool ADD_BIAS>
__global__ void __launch_bounds__(256) gemm_kernel(
    const float* __restrict__ A,
    const float* __restrict__ Wall,
    const float* __restrict__ bias,
    float* __restrict__ Call)
{
    constexpr int BM = 64, BK = 32;
    constexpr int TN = DOUT / 16;   // 8 (DOUT=128) or 4 (DOUT=64)
    constexpr int TM = 4;
    __shared__ float At[BM][BK];
    __shared__ float Wt[BK][DOUT];

    const float* W = Wall + (size_t)blockIdx.z * 128 * DOUT;
    float* C = Call + (size_t)blockIdx.z * NN * DOUT;

    const int tid = threadIdx.x;
    const int tx = tid & 15, ty = tid >> 4;
    const int rowBase = blockIdx.x * BM;

    float acc[TM][TN];
    #pragma unroll
    for (int i = 0; i < TM; i++)
        #pragma unroll
        for (int j = 0; j < TN; j++) acc[i][j] = 0.f;

    for (int k0 = 0; k0 < 128; k0 += BK) {
        // A tile: 64x32 = 512 float4, 2 per thread
        #pragma unroll
        for (int t = 0; t < 2; t++) {
            int idx = tid + t * 256;
            int r = idx >> 3;
            int kq = idx & 7;
            int grow = rowBase + r;
            float4 v = make_float4(0.f, 0.f, 0.f, 0.f);
            if (grow < NN)
                v = *(const float4*)(A + (size_t)grow * 128 + k0 + kq * 4);
            if (RELU_IN) {
                v.x = fmaxf(v.x, 0.f); v.y = fmaxf(v.y, 0.f);
                v.z = fmaxf(v.z, 0.f); v.w = fmaxf(v.w, 0.f);
            }
            *(float4*)(&At[r][kq * 4]) = v;
        }
        // W tile: BK x DOUT
        constexpr int WF4 = (BK * DOUT / 4) / 256;  // 4 or 2
        #pragma unroll
        for (int t = 0; t < WF4; t++) {
            int idx = tid + t * 256;
            int kk = idx / (DOUT / 4);
            int oq = idx % (DOUT / 4);
            float4 v = *(const float4*)(W + (size_t)(k0 + kk) * DOUT + oq * 4);
            *(float4*)(&Wt[kk][oq * 4]) = v;
        }
        __syncthreads();

        #pragma unroll
        for (int k = 0; k < BK; k++) {
            float a[TM];
            #pragma unroll
            for (int i = 0; i < TM; i++) a[i] = At[ty * TM + i][k];
            float w[TN];
            #pragma unroll
            for (int j = 0; j < TN; j += 4) {
                float4 wv = *(const float4*)(&Wt[k][tx * TN + j]);
                w[j] = wv.x; w[j + 1] = wv.y; w[j + 2] = wv.z; w[j + 3] = wv.w;
            }
            #pragma unroll
            for (int i = 0; i < TM; i++)
                #pragma unroll
                for (int j = 0; j < TN; j++)
                    acc[i][j] = fmaf(a[i], w[j], acc[i][j]);
        }
        __syncthreads();
    }

    #pragma unroll
    for (int i = 0; i < TM; i++) {
        int grow = rowBase + ty * TM + i;
        if (grow >= NN) continue;
        #pragma unroll
        for (int j = 0; j < TN; j += 4) {
            int col = tx * TN + j;
            float4 v = make_float4(acc[i][j], acc[i][j + 1], acc[i][j + 2], acc[i][j + 3]);
            if (ADD_BIAS) {
                v.x += bias[col];     v.y += bias[col + 1];
                v.z += bias[col + 2]; v.w += bias[col + 3];
            }
            *(float4*)(C + (size_t)grow * DOUT + col) = v;
        }
    }
}

// out[dst[e], :] += rel[et[e], src[e], :]
template<int DOUT>
__global__ void __launch_bounds__(256) scatter_kernel(
    const int* __restrict__ src,
    const int* __restrict__ dst,
    const int* __restrict__ et,
    const float* __restrict__ rel,
    float* __restrict__ out)
{
    constexpr int LPE = DOUT / 4;    // lanes per edge: 32 or 16
    constexpr int EPW = 32 / LPE;    // edges per warp:  1 or 2
    int warp = (blockIdx.x * blockDim.x + threadIdx.x) >> 5;
    int lane = threadIdx.x & 31;
    int e = warp * EPW + lane / LPE;
    if (e >= NE) return;
    int l = lane % LPE;
    int s = src[e], d = dst[e], r = et[e];
    float4 v = *(const float4*)(rel + ((size_t)r * NN + s) * DOUT + l * 4);
    float* o = out + (size_t)d * DOUT + l * 4;
    atomicAdd(o + 0, v.x);
    atomicAdd(o + 1, v.y);
    atomicAdd(o + 2, v.z);
    atomicAdd(o + 3, v.w);
}

extern "C" void kernel_launch(void* const* d_in, const int* in_sizes, int n_in,
                              void* d_out, int out_size)
{
    const float* feat = (const float*)d_in[0];
    const int*   src  = (const int*)d_in[1];
    const int*   dst  = (const int*)d_in[2];
    const int*   et   = (const int*)d_in[3];
    const float* W1   = (const float*)d_in[4];
    const float* W1s  = (const float*)d_in[5];
    const float* b1   = (const float*)d_in[6];
    const float* W2   = (const float*)d_in[7];
    const float* W2s  = (const float*)d_in[8];
    const float* b2   = (const float*)d_in[9];
    float* out = (float*)d_out;

    float *rel1, *rel2, *h1;
    cudaGetSymbolAddress((void**)&rel1, g_rel1);
    cudaGetSymbolAddress((void**)&rel2, g_rel2);
    cudaGetSymbolAddress((void**)&h1, g_h1);

    dim3 blk(256);
    int gm = (NN + 63) / 64;  // 782

    // Layer 1
    gemm_kernel<128, false, false><<<dim3(gm, 1, NR), blk>>>(feat, W1, nullptr, rel1);
    gemm_kernel<128, false, true ><<<dim3(gm, 1, 1 ), blk>>>(feat, W1s, b1, h1);
    scatter_kernel<128><<<(NE + 7) / 8, blk>>>(src, dst, et, rel1, h1);

    // Layer 2 (ReLU fused on reads of h1)
    gemm_kernel<64, true, false><<<dim3(gm, 1, NR), blk>>>(h1, W2, nullptr, rel2);
    gemm_kernel<64, true, true ><<<dim3(gm, 1, 1 ), blk>>>(h1, W2s, b2, out);
    scatter_kernel<64><<<(NE + 15) / 16, blk>>>(src, dst, et, rel2, out);
}

// round 4
// speedup vs baseline: 1.0020x; 1.0020x over previous
#include <cuda_runtime.h>

#define NN 50000
#define NE 640000
#define NR 8
#define D1 128   // IN_DIM == HID_DIM
#define D2 64    // OUT_DIM

// Scratch (allocation-free rule: __device__ globals)
__device__ float g_rel1[(size_t)NR * NN * D1]; // 204.8 MB
__device__ float g_rel2[(size_t)NR * NN * D2]; // 102.4 MB
__device__ float g_h1[(size_t)NN * D1];        // 25.6 MB

// C[z] = (relu?)(A) @ W[z] (+ bias), A:[NN,128], W:[Z,128,DOUT], C:[Z,NN,DOUT]
template<int DOUT, bool RELU_IN, bool ADD_BIAS>
__global__ void __launch_bounds__(256) gemm_kernel(
    const float* __restrict__ A,
    const float* __restrict__ Wall,
    const float* __restrict__ bias,
    float* __restrict__ Call)
{
    constexpr int BM = 64, BK = 32;
    constexpr int TN = DOUT / 16;   // 8 (DOUT=128) or 4 (DOUT=64)
    constexpr int TM = 4;
    __shared__ float At[BM][BK];
    __shared__ float Wt[BK][DOUT];

    const float* W = Wall + (size_t)blockIdx.z * 128 * DOUT;
    float* C = Call + (size_t)blockIdx.z * NN * DOUT;

    const int tid = threadIdx.x;
    const int tx = tid & 15, ty = tid >> 4;
    const int rowBase = blockIdx.x * BM;

    float acc[TM][TN];
    #pragma unroll
    for (int i = 0; i < TM; i++)
        #pragma unroll
        for (int j = 0; j < TN; j++) acc[i][j] = 0.f;

    for (int k0 = 0; k0 < 128; k0 += BK) {
        // A tile: 64x32 = 512 float4, 2 per thread
        #pragma unroll
        for (int t = 0; t < 2; t++) {
            int idx = tid + t * 256;
            int r = idx >> 3;
            int kq = idx & 7;
            int grow = rowBase + r;
            float4 v = make_float4(0.f, 0.f, 0.f, 0.f);
            if (grow < NN)
                v = *(const float4*)(A + (size_t)grow * 128 + k0 + kq * 4);
            if (RELU_IN) {
                v.x = fmaxf(v.x, 0.f); v.y = fmaxf(v.y, 0.f);
                v.z = fmaxf(v.z, 0.f); v.w = fmaxf(v.w, 0.f);
            }
            *(float4*)(&At[r][kq * 4]) = v;
        }
        // W tile: BK x DOUT
        constexpr int WF4 = (BK * DOUT / 4) / 256;  // 4 or 2
        #pragma unroll
        for (int t = 0; t < WF4; t++) {
            int idx = tid + t * 256;
            int kk = idx / (DOUT / 4);
            int oq = idx % (DOUT / 4);
            float4 v = *(const float4*)(W + (size_t)(k0 + kk) * DOUT + oq * 4);
            *(float4*)(&Wt[kk][oq * 4]) = v;
        }
        __syncthreads();

        #pragma unroll
        for (int k = 0; k < BK; k++) {
            float a[TM];
            #pragma unroll
            for (int i = 0; i < TM; i++) a[i] = At[ty * TM + i][k];
            float w[TN];
            #pragma unroll
            for (int j = 0; j < TN; j += 4) {
                float4 wv = *(const float4*)(&Wt[k][tx * TN + j]);
                w[j] = wv.x; w[j + 1] = wv.y; w[j + 2] = wv.z; w[j + 3] = wv.w;
            }
            #pragma unroll
            for (int i = 0; i < TM; i++)
                #pragma unroll
                for (int j = 0; j < TN; j++)
                    acc[i][j] = fmaf(a[i], w[j], acc[i][j]);
        }
        __syncthreads();
    }

    #pragma unroll
    for (int i = 0; i < TM; i++) {
        int grow = rowBase + ty * TM + i;
        if (grow >= NN) continue;
        #pragma unroll
        for (int j = 0; j < TN; j += 4) {
            int col = tx * TN + j;
            float4 v = make_float4(acc[i][j], acc[i][j + 1], acc[i][j + 2], acc[i][j + 3]);
            if (ADD_BIAS) {
                v.x += bias[col];     v.y += bias[col + 1];
                v.z += bias[col + 2]; v.w += bias[col + 3];
            }
            *(float4*)(C + (size_t)grow * DOUT + col) = v;
        }
    }
}

// out[dst[e], :] += rel[et[e], src[e], :]
template<int DOUT>
__global__ void __launch_bounds__(256) scatter_kernel(
    const int* __restrict__ src,
    const int* __restrict__ dst,
    const int* __restrict__ et,
    const float* __restrict__ rel,
    float* __restrict__ out)
{
    constexpr int LPE = DOUT / 4;    // lanes per edge: 32 or 16
    constexpr int EPW = 32 / LPE;    // edges per warp:  1 or 2
    int warp = (blockIdx.x * blockDim.x + threadIdx.x) >> 5;
    int lane = threadIdx.x & 31;
    int e = warp * EPW + lane / LPE;
    if (e >= NE) return;
    int l = lane % LPE;
    int s = src[e], d = dst[e], r = et[e];
    float4 v = *(const float4*)(rel + ((size_t)r * NN + s) * DOUT + l * 4);
    float* o = out + (size_t)d * DOUT + l * 4;
    atomicAdd(o + 0, v.x);
    atomicAdd(o + 1, v.y);
    atomicAdd(o + 2, v.z);
    atomicAdd(o + 3, v.w);
}

extern "C" void kernel_launch(void* const* d_in, const int* in_sizes, int n_in,
                              void* d_out, int out_size)
{
    const float* feat = (const float*)d_in[0];
    const int*   src  = (const int*)d_in[1];
    const int*   dst  = (const int*)d_in[2];
    const int*   et   = (const int*)d_in[3];
    const float* W1   = (const float*)d_in[4];
    const float* W1s  = (const float*)d_in[5];
    const float* b1   = (const float*)d_in[6];
    const float* W2   = (const float*)d_in[7];
    const float* W2s  = (const float*)d_in[8];
    const float* b2   = (const float*)d_in[9];
    float* out = (float*)d_out;

    float *rel1, *rel2, *h1;
    cudaGetSymbolAddress((void**)&rel1, g_rel1);
    cudaGetSymbolAddress((void**)&rel2, g_rel2);
    cudaGetSymbolAddress((void**)&h1, g_h1);

    dim3 blk(256);
    int gm = (NN + 63) / 64;  // 782

    // Layer 1
    gemm_kernel<128, false, false><<<dim3(gm, 1, NR), blk>>>(feat, W1, nullptr, rel1);
    gemm_kernel<128, false, true ><<<dim3(gm, 1, 1 ), blk>>>(feat, W1s, b1, h1);
    scatter_kernel<128><<<(NE + 7) / 8, blk>>>(src, dst, et, rel1, h1);

    // Layer 2 (ReLU fused on reads of h1)
    gemm_kernel<64, true, false><<<dim3(gm, 1, NR), blk>>>(h1, W2, nullptr, rel2);
    gemm_kernel<64, true, true ><<<dim3(gm, 1, 1 ), blk>>>(h1, W2s, b2, out);
    scatter_kernel<64><<<(NE + 15) / 16, blk>>>(src, dst, et, rel2, out);
}